// round 4
// baseline (speedup 1.0000x reference)
#include <cuda_runtime.h>
#include <cstdint>

// Problem shape (fixed for this dataset):
//   pool: f32  [16, 128, 128, 64]  -> 16,777,216 elements
//   ind : i32  same shape, values in [0, 4,194,304)
//   out : f32  [16, 256, 256, 64]  -> 67,108,864 elements (256 MB)
// Per-batch flat scatter-ADD (duplicates sum).
//
// Strategy:
//  - 4 chunks x 4 batches: zero chunk (cudaMemsetAsync) then scatter while the
//    64 MB output slice is L2-resident (L2 = 126 MB).
//  - Scatter kernel is persistent/grid-stride: each thread handles many
//    vec4 groups with next-iteration loads pipelined ahead of the current
//    atomics, so the LSU always has deep outstanding REDG work (fixes the
//    R3 profile: issue=4%, nothing saturated => concurrency-bound).

static constexpr int  PB_IN_V4_LOG2     = 18;   // per-batch input elems/4 = 2^18
static constexpr int  OUT_FLAT_LOG2     = 22;   // per-batch output elems = 2^22
static constexpr int  BATCHES           = 16;
static constexpr int  BATCHES_PER_CHUNK = 4;
static constexpr int  NCHUNKS           = BATCHES / BATCHES_PER_CHUNK;

static constexpr int  CHUNK_IN_V4    = BATCHES_PER_CHUNK << PB_IN_V4_LOG2;        // 1,048,576
static constexpr long CHUNK_OUT_ELEM = (long)BATCHES_PER_CHUNK << OUT_FLAT_LOG2;  // 16,777,216

static constexpr int  THREADS = 256;
static constexpr int  BLOCKS  = 148 * 8;   // persistent-ish: ~1 wave at occupancy

// ---------------------------------------------------------------------------
// Grid-stride scatter-add for one chunk (BATCHES_PER_CHUNK batches).
// Software-pipelined: loads for iteration k+1 are issued before the atomics
// of iteration k, keeping independent memory ops in flight.
// ---------------------------------------------------------------------------
__global__ void __launch_bounds__(THREADS)
unpool_scatter_chunk(const float4* __restrict__ pool4,
                     const int4*   __restrict__ ind4,
                     float*        __restrict__ out,
                     int n4) {
    const int stride = gridDim.x * blockDim.x;
    int t = blockIdx.x * blockDim.x + threadIdx.x;

    if (t >= n4) return;

    // Prologue: load first group.
    float4 p = pool4[t];
    int4   i = ind4[t];

    int next = t + stride;
    while (next < n4) {
        // Issue next iteration's loads before this iteration's atomics (MLP).
        float4 pn = pool4[next];
        int4   in = ind4[next];

        long base = (long)(t >> PB_IN_V4_LOG2) << OUT_FLAT_LOG2;
        atomicAdd(out + base + (long)(unsigned)i.x, p.x);
        atomicAdd(out + base + (long)(unsigned)i.y, p.y);
        atomicAdd(out + base + (long)(unsigned)i.z, p.z);
        atomicAdd(out + base + (long)(unsigned)i.w, p.w);

        p = pn; i = in; t = next;
        next = t + stride;
    }

    // Epilogue: last group.
    long base = (long)(t >> PB_IN_V4_LOG2) << OUT_FLAT_LOG2;
    atomicAdd(out + base + (long)(unsigned)i.x, p.x);
    atomicAdd(out + base + (long)(unsigned)i.y, p.y);
    atomicAdd(out + base + (long)(unsigned)i.z, p.z);
    atomicAdd(out + base + (long)(unsigned)i.w, p.w);
}

// ---------------------------------------------------------------------------
extern "C" void kernel_launch(void* const* d_in, const int* in_sizes, int n_in,
                              void* d_out, int out_size) {
    const float4* pool4 = (const float4*)d_in[0];
    const int4*   ind4  = (const int4*)d_in[1];
    float*        out   = (float*)d_out;

    for (int c = 0; c < NCHUNKS; ++c) {
        float* out_chunk = out + (long)c * CHUNK_OUT_ELEM;

        // Zero this chunk's output slice (stays L2-resident for the scatter).
        cudaMemsetAsync(out_chunk, 0, CHUNK_OUT_ELEM * sizeof(float), 0);

        // Scatter-add this chunk's 4 batches while the slice is hot in L2.
        unpool_scatter_chunk<<<BLOCKS, THREADS>>>(
            pool4 + (long)c * CHUNK_IN_V4,
            ind4  + (long)c * CHUNK_IN_V4,
            out_chunk,
            CHUNK_IN_V4);
    }
}

// round 5
// speedup vs baseline: 1.0200x; 1.0200x over previous
#include <cuda_runtime.h>
#include <cstdint>

// Problem shape (fixed for this dataset):
//   pool: f32  [16, 128, 128, 64]  -> 16,777,216 elements
//   ind : i32  same shape, values in [0, 4,194,304)
//   out : f32  [16, 256, 256, 64]  -> 67,108,864 elements (256 MB)
// Per-batch flat scatter-ADD (duplicates sum).
//
// Strategy:
//  - 4 chunks x 4 batches: memset chunk slice, then scatter while the 64 MB
//    slice is L2-resident (L2 = 126 MB).
//  - Scatter kernel: each thread owns TWO coalesced vec4 groups with all
//    loads front-batched, then 8 independent REDG atomics. Goal: keep >=2
//    REDG instructions replaying concurrently per warp so the L1tex
//    wavefront engine interleaves replays (~1.0 cyc/wf cross-instruction)
//    instead of serializing one instruction's replays (2.07 cyc/wf —
//    which is exactly the floor R3 measured at 34 us/chunk).

static constexpr int  PB_IN_V4_LOG2     = 18;   // per-batch input elems/4 = 2^18
static constexpr int  OUT_FLAT_LOG2     = 22;   // per-batch output elems = 2^22
static constexpr int  BATCHES           = 16;
static constexpr int  BATCHES_PER_CHUNK = 4;
static constexpr int  NCHUNKS           = BATCHES / BATCHES_PER_CHUNK;

static constexpr int  CHUNK_IN_V4    = BATCHES_PER_CHUNK << PB_IN_V4_LOG2;        // 1,048,576
static constexpr long CHUNK_OUT_ELEM = (long)BATCHES_PER_CHUNK << OUT_FLAT_LOG2;  // 16,777,216

static constexpr int  THREADS = 256;

// ---------------------------------------------------------------------------
// Scatter-add for one chunk: 2 vec4 groups per thread, 8 atomics in flight.
// Group addresses t and t + n4/2 are both fully coalesced.
// ---------------------------------------------------------------------------
__global__ void __launch_bounds__(THREADS)
unpool_scatter_chunk2(const float4* __restrict__ pool4,
                      const int4*   __restrict__ ind4,
                      float*        __restrict__ out,
                      int n4half) {
    int t = blockIdx.x * blockDim.x + threadIdx.x;
    if (t >= n4half) return;
    int t2 = t + n4half;

    // Front-batch ALL loads (4 independent 16B loads -> deep MLP)
    float4 p0 = pool4[t];
    float4 p1 = pool4[t2];
    int4   i0 = ind4[t];
    int4   i1 = ind4[t2];

    long b0 = (long)(t  >> PB_IN_V4_LOG2) << OUT_FLAT_LOG2;
    long b1 = (long)(t2 >> PB_IN_V4_LOG2) << OUT_FLAT_LOG2;

    // 8 independent no-return atomics (REDG): two instruction streams the
    // L1tex replay engine can interleave.
    atomicAdd(out + b0 + (long)(unsigned)i0.x, p0.x);
    atomicAdd(out + b1 + (long)(unsigned)i1.x, p1.x);
    atomicAdd(out + b0 + (long)(unsigned)i0.y, p0.y);
    atomicAdd(out + b1 + (long)(unsigned)i1.y, p1.y);
    atomicAdd(out + b0 + (long)(unsigned)i0.z, p0.z);
    atomicAdd(out + b1 + (long)(unsigned)i1.z, p1.z);
    atomicAdd(out + b0 + (long)(unsigned)i0.w, p0.w);
    atomicAdd(out + b1 + (long)(unsigned)i1.w, p1.w);
}

// ---------------------------------------------------------------------------
extern "C" void kernel_launch(void* const* d_in, const int* in_sizes, int n_in,
                              void* d_out, int out_size) {
    const float4* pool4 = (const float4*)d_in[0];
    const int4*   ind4  = (const int4*)d_in[1];
    float*        out   = (float*)d_out;

    const int n4half = CHUNK_IN_V4 / 2;                       // 524,288
    const int blocks = (n4half + THREADS - 1) / THREADS;      // 2,048

    for (int c = 0; c < NCHUNKS; ++c) {
        float* out_chunk = out + (long)c * CHUNK_OUT_ELEM;

        // Zero this chunk's output slice (stays L2-resident for the scatter).
        cudaMemsetAsync(out_chunk, 0, CHUNK_OUT_ELEM * sizeof(float), 0);

        // Scatter-add this chunk's 4 batches while the slice is hot in L2.
        unpool_scatter_chunk2<<<blocks, THREADS>>>(
            pool4 + (long)c * CHUNK_IN_V4,
            ind4  + (long)c * CHUNK_IN_V4,
            out_chunk,
            n4half);
    }
}

// round 6
// speedup vs baseline: 1.0671x; 1.0462x over previous
#include <cuda_runtime.h>
#include <cstdint>

// Problem shape (fixed for this dataset):
//   pool: f32  [16, 128, 128, 64]  -> 16,777,216 elements
//   ind : i32  same shape, values in [0, 4,194,304)
//   out : f32  [16, 256, 256, 64]  -> 67,108,864 elements (256 MB)
// Per-batch flat scatter-ADD (duplicates sum).
//
// Pipeline: 8 chunks of 2 batches. Kernel k scatters chunk k (atomics into
// its L2-resident 32 MB slice) while extra blocks in the SAME kernel zero
// chunk k+1's slice (streaming stores -> dirty L2 lines, nearly free since
// the scatter is atomic-replay-bound: DRAM 40%, issue 3.4%).
// L2 live set: 32 MB cur + 32 MB next + ~16 MB inputs = 80 MB < 126 MB.
//
// Measured walls so far: scatter floor ~2.07 cyc/atomic/SM => ~131 us for
// 16.7M atomics; this round removes the ~12-20 us of serialized memsets.

static constexpr int  PB_IN_V4_LOG2     = 18;   // per-batch input elems/4 = 2^18
static constexpr int  OUT_FLAT_LOG2     = 22;   // per-batch output elems = 2^22
static constexpr int  BATCHES           = 16;
static constexpr int  BATCHES_PER_CHUNK = 2;
static constexpr int  NCHUNKS           = BATCHES / BATCHES_PER_CHUNK;   // 8

static constexpr int  CHUNK_IN_V4    = BATCHES_PER_CHUNK << PB_IN_V4_LOG2;        // 524,288
static constexpr long CHUNK_OUT_ELEM = (long)BATCHES_PER_CHUNK << OUT_FLAT_LOG2;  // 8,388,608
static constexpr int  CHUNK_OUT_V4   = (int)(CHUNK_OUT_ELEM / 4);                 // 2,097,152

static constexpr int  THREADS        = 256;
static constexpr int  SCATTER_BLOCKS = CHUNK_IN_V4 / THREADS;   // 2048
static constexpr int  ZERO_BLOCKS    = 512;                     // 16 float4 stores/thread

// ---------------------------------------------------------------------------
// Fused kernel: blocks [0, SCATTER_BLOCKS) scatter chunk k;
//               blocks [SCATTER_BLOCKS, +ZERO_BLOCKS) zero chunk k+1.
// zero_dst == nullptr on the last chunk (no next slice to zero).
// ---------------------------------------------------------------------------
__global__ void __launch_bounds__(THREADS)
unpool_fused(const float4* __restrict__ pool4,
             const int4*   __restrict__ ind4,
             float*        __restrict__ out,
             float4*       __restrict__ zero_dst) {
    int bid = blockIdx.x;

    if (bid < SCATTER_BLOCKS) {
        // ---- scatter chunk k (R3-proven body) ----
        int t = bid * THREADS + threadIdx.x;

        float4 p = pool4[t];            // front-batched loads (MLP)
        int4   i = ind4[t];

        long base = (long)(t >> PB_IN_V4_LOG2) << OUT_FLAT_LOG2;

        atomicAdd(out + base + (long)(unsigned)i.x, p.x);
        atomicAdd(out + base + (long)(unsigned)i.y, p.y);
        atomicAdd(out + base + (long)(unsigned)i.z, p.z);
        atomicAdd(out + base + (long)(unsigned)i.w, p.w);
    } else if (zero_dst != nullptr) {
        // ---- zero chunk k+1 (grid-stride streaming stores) ----
        const float4 z = make_float4(0.f, 0.f, 0.f, 0.f);
        int zt = (bid - SCATTER_BLOCKS) * THREADS + threadIdx.x;
        const int zstride = ZERO_BLOCKS * THREADS;
        #pragma unroll 4
        for (; zt < CHUNK_OUT_V4; zt += zstride) {
            zero_dst[zt] = z;
        }
    }
}

// Pure zero kernel for chunk 0 (before the pipeline starts).
__global__ void __launch_bounds__(THREADS)
zero_chunk(float4* __restrict__ dst) {
    const float4 z = make_float4(0.f, 0.f, 0.f, 0.f);
    int t = blockIdx.x * blockDim.x + threadIdx.x;
    const int stride = gridDim.x * blockDim.x;
    for (; t < CHUNK_OUT_V4; t += stride) {
        dst[t] = z;
    }
}

// ---------------------------------------------------------------------------
extern "C" void kernel_launch(void* const* d_in, const int* in_sizes, int n_in,
                              void* d_out, int out_size) {
    const float4* pool4 = (const float4*)d_in[0];
    const int4*   ind4  = (const int4*)d_in[1];
    float*        out   = (float*)d_out;

    // Zero chunk 0 up front (wide grid: this one is latency-exposed).
    zero_chunk<<<2048, THREADS>>>((float4*)out);

    for (int c = 0; c < NCHUNKS; ++c) {
        float* out_cur  = out + (long)c * CHUNK_OUT_ELEM;
        float4* zero_nx = (c + 1 < NCHUNKS)
                        ? (float4*)(out + (long)(c + 1) * CHUNK_OUT_ELEM)
                        : nullptr;

        int grid = SCATTER_BLOCKS + (zero_nx ? ZERO_BLOCKS : 0);
        unpool_fused<<<grid, THREADS>>>(
            pool4 + (long)c * CHUNK_IN_V4,
            ind4  + (long)c * CHUNK_IN_V4,
            out_cur,
            zero_nx);
    }
}